// round 15
// baseline (speedup 1.0000x reference)
#include <cuda_runtime.h>
#include <cuda_fp16.h>

#define NN 50000
#define NE 600000
#define NT (NE + NN)
#define NE4 (NE / 4)
#define HID 128
#define NG 128
#define NC 5
#define NBLK ((NN + 255) / 256)   // 196

__device__ __forceinline__ unsigned h2_as_u(__half2 h) {
    return *reinterpret_cast<unsigned*>(&h);
}
__device__ __forceinline__ __half2 u_as_h2(unsigned u) {
    return *reinterpret_cast<__half2*>(&u);
}

// ---------------- device scratch (no allocs allowed) ----------------
// invariant: g_cnt is all-zero on entry to kernel_launch (zero-init on load;
// k_scan1 resets it each call after k_deg consumed the counts).
__device__ int    g_cnt[NN];
__device__ float  g_dis[NN];
__device__ int    g_rowptr[NN + 1];
__device__ int    g_aggflag[NBLK];               // bit30 = ready; cleared by k_deg
__device__ int    g_pos[NE];                     // per-edge slot within its row
__device__ int    g_col[NT];                     // CSR columns (norm folded into nodes)
__device__ __align__(16) float4 g_xs4[NN];       // dis[n] * x[n], padded to float4
__device__ __align__(16) __half g_hh[NN * HID];  // activations (fp16)
__device__ __align__(16) __half g_ah[NN * HID];  // aggregated (fp16)

// ---------------- degree count + slot assignment (4-way MLP) ----------------
__global__ void k_deg(const int* __restrict__ dst) {
    int t = blockIdx.x * blockDim.x + threadIdx.x;
    if (t < NBLK) g_aggflag[t] = 0;              // reset lookback flags for k_scan1
    if (t >= NE4) return;
    int d0 = dst[t];
    int d1 = dst[t + NE4];
    int d2 = dst[t + 2 * NE4];
    int d3 = dst[t + 3 * NE4];
    int p0 = atomicAdd(&g_cnt[d0], 1);
    int p1 = atomicAdd(&g_cnt[d1], 1);
    int p2 = atomicAdd(&g_cnt[d2], 1);
    int p3 = atomicAdd(&g_cnt[d3], 1);
    g_pos[t]           = p0;
    g_pos[t + NE4]     = p1;
    g_pos[t + 2 * NE4] = p2;
    g_pos[t + 3 * NE4] = p3;
}

__device__ __forceinline__ int block_excl_scan_256(int v, int tid, int* wsum) {
    int lane = tid & 31, wid = tid >> 5;
    int x = v;
    #pragma unroll
    for (int o = 1; o < 32; o <<= 1) {
        int y = __shfl_up_sync(0xffffffffu, x, o);
        if (lane >= o) x += y;
    }
    if (lane == 31) wsum[wid] = x;
    __syncthreads();
    if (wid == 0) {
        int w = (lane < 8) ? wsum[lane] : 0;
        #pragma unroll
        for (int o = 1; o < 8; o <<= 1) {
            int y = __shfl_up_sync(0xffffffffu, w, o);
            if (lane >= o) w += y;
        }
        if (lane < 8) wsum[lane] = w;
    }
    __syncthreads();
    return x - v + (wid ? wsum[wid - 1] : 0);
}

// single-pass scan with lookback; computes dis, xs4 = dis*x, resets cnt,
// and pre-places the self loop at slot 0 of each CSR row.
__global__ void k_scan1(const float* __restrict__ x) {
    __shared__ int wsum[8];
    __shared__ int rsum[8];
    __shared__ int s_total;
    __shared__ int s_pre;
    int tid = threadIdx.x;
    int b = blockIdx.x;
    int i = b * 256 + tid;
    int v = 0;
    if (i < NN) {
        v = g_cnt[i] + 1;             // +1: self loop
        float dis = rsqrtf((float)v);
        g_dis[i] = dis;
        g_xs4[i] = make_float4(dis * x[i * 3 + 0], dis * x[i * 3 + 1],
                               dis * x[i * 3 + 2], 0.f);
        g_cnt[i] = 0;                 // restore all-zero invariant for next call
    }
    int excl = block_excl_scan_256(v, tid, wsum);
    if (tid == 255) s_total = excl + v;
    __syncthreads();
    if (tid == 0) atomicExch(&g_aggflag[b], 0x40000000 | s_total);
    int pre = 0;
    if (tid < b) {
        int f;
        do { f = atomicAdd(&g_aggflag[tid], 0); } while (!(f & 0x40000000));
        pre = f & 0x3fffffff;
    }
    int lane = tid & 31, wid = tid >> 5;
    #pragma unroll
    for (int o = 16; o; o >>= 1) pre += __shfl_down_sync(0xffffffffu, pre, o);
    if (lane == 0) rsum[wid] = pre;
    __syncthreads();
    if (wid == 0) {
        int w = (lane < 8) ? rsum[lane] : 0;
        #pragma unroll
        for (int o = 4; o; o >>= 1) w += __shfl_down_sync(0xffffffffu, w, o);
        if (lane == 0) s_pre = w;
    }
    __syncthreads();
    if (i < NN) {
        int rp = excl + s_pre;
        g_rowptr[i] = rp;
        g_col[rp] = i;                // self loop occupies slot 0
    }
    if (b == 0 && tid == 0) g_rowptr[NN] = NT;
}

// atomic-free scatter: 4 independent load->store chains per thread
__global__ void k_fill(const int* __restrict__ src, const int* __restrict__ dst) {
    int t = blockIdx.x * blockDim.x + threadIdx.x;
    if (t >= NE4) return;
    #pragma unroll
    for (int q = 0; q < 4; q++) {
        int e = t + q * NE4;
        int s = src[e];
        int d = dst[e];
        int p = g_pos[e];
        g_col[g_rowptr[d] + 1 + p] = s;
    }
}

// ---------------- layer 1: h1' = dis * relu( dis*(sum xs4) @ W1 + b1 ) ----------------
__global__ void k_layer1(const float* __restrict__ W1, const float* __restrict__ b1) {
    int node = blockIdx.x * 8 + (threadIdx.x >> 5);
    if (node >= NN) return;
    int lane = threadIdx.x & 31;
    int beg = g_rowptr[node], end = g_rowptr[node + 1];
    float a0 = 0.f, a1 = 0.f, a2 = 0.f;
    for (int j = beg + lane; j < end; j += 32) {
        float4 v = g_xs4[g_col[j]];
        a0 += v.x; a1 += v.y; a2 += v.z;
    }
    #pragma unroll
    for (int o = 16; o; o >>= 1) {
        a0 += __shfl_down_sync(0xffffffffu, a0, o);
        a1 += __shfl_down_sync(0xffffffffu, a1, o);
        a2 += __shfl_down_sync(0xffffffffu, a2, o);
    }
    float dis = g_dis[node];
    a0 = __shfl_sync(0xffffffffu, a0, 0) * dis;
    a1 = __shfl_sync(0xffffffffu, a1, 0) * dis;
    a2 = __shfl_sync(0xffffffffu, a2, 0) * dis;
    int c = lane * 4;
    float v0 = dis * fmaxf(a0 * W1[c+0] + a1 * W1[128+c+0] + a2 * W1[256+c+0] + b1[c+0], 0.f);
    float v1 = dis * fmaxf(a0 * W1[c+1] + a1 * W1[128+c+1] + a2 * W1[256+c+1] + b1[c+1], 0.f);
    float v2 = dis * fmaxf(a0 * W1[c+2] + a1 * W1[128+c+2] + a2 * W1[256+c+2] + b1[c+2], 0.f);
    float v3 = dis * fmaxf(a0 * W1[c+3] + a1 * W1[128+c+3] + a2 * W1[256+c+3] + b1[c+3], 0.f);
    uint2 p;
    p.x = h2_as_u(__float22half2_rn(make_float2(v0, v1)));
    p.y = h2_as_u(__float22half2_rn(make_float2(v2, v3)));
    *(uint2*)(g_hh + (size_t)node * 128 + c) = p;
}

// ---------------- propagate: g_ah[d] = dis[d] * sum_{s in N(d)} g_hh[s] ----------------
__global__ void k_prop() {
    int node = blockIdx.x * 8 + (threadIdx.x >> 5);
    if (node >= NN) return;
    int lane = threadIdx.x & 31;
    int beg = g_rowptr[node], end = g_rowptr[node + 1];
    float4 acc  = make_float4(0.f, 0.f, 0.f, 0.f);
    float4 acc2 = make_float4(0.f, 0.f, 0.f, 0.f);
    int j = beg;
    for (; j + 3 < end; j += 4) {
        int s0c = g_col[j],     s1c = g_col[j + 1];
        int s2c = g_col[j + 2], s3c = g_col[j + 3];
        uint2 h0 = *(const uint2*)(g_hh + (size_t)s0c * 128 + lane * 4);
        uint2 h1 = *(const uint2*)(g_hh + (size_t)s1c * 128 + lane * 4);
        uint2 h2 = *(const uint2*)(g_hh + (size_t)s2c * 128 + lane * 4);
        uint2 h3 = *(const uint2*)(g_hh + (size_t)s3c * 128 + lane * 4);
        float2 p0 = __half22float2(u_as_h2(h0.x)), p1 = __half22float2(u_as_h2(h0.y));
        float2 q0 = __half22float2(u_as_h2(h1.x)), q1 = __half22float2(u_as_h2(h1.y));
        float2 r0 = __half22float2(u_as_h2(h2.x)), r1 = __half22float2(u_as_h2(h2.y));
        float2 t0 = __half22float2(u_as_h2(h3.x)), t1 = __half22float2(u_as_h2(h3.y));
        acc.x  += p0.x; acc.y  += p0.y; acc.z  += p1.x; acc.w  += p1.y;
        acc2.x += q0.x; acc2.y += q0.y; acc2.z += q1.x; acc2.w += q1.y;
        acc.x  += r0.x; acc.y  += r0.y; acc.z  += r1.x; acc.w  += r1.y;
        acc2.x += t0.x; acc2.y += t0.y; acc2.z += t1.x; acc2.w += t1.y;
    }
    for (; j < end; j++) {
        uint2 h = *(const uint2*)(g_hh + (size_t)g_col[j] * 128 + lane * 4);
        float2 p0 = __half22float2(u_as_h2(h.x));
        float2 p1 = __half22float2(u_as_h2(h.y));
        acc.x += p0.x; acc.y += p0.y; acc.z += p1.x; acc.w += p1.y;
    }
    float dis = g_dis[node];
    acc.x = (acc.x + acc2.x) * dis; acc.y = (acc.y + acc2.y) * dis;
    acc.z = (acc.z + acc2.z) * dis; acc.w = (acc.w + acc2.w) * dis;
    uint2 o;
    o.x = h2_as_u(__float22half2_rn(make_float2(acc.x, acc.y)));
    o.y = h2_as_u(__float22half2_rn(make_float2(acc.z, acc.w)));
    *(uint2*)(g_ah + (size_t)node * 128 + lane * 4) = o;
}

// ---------------- GEMM (HMMA): g_hh = [dis*] relu(g_ah @ W + b) ----------------
#define PA 72    // A smem pitch (halfs)
#define PB 136   // B smem pitch (halfs)

__global__ __launch_bounds__(256, 2) void k_gemm(const float* __restrict__ W,
                                                 const float* __restrict__ bias,
                                                 int scale_out) {
    __shared__ __align__(16) __half As[128 * PA];  // 18KB
    __shared__ __align__(16) __half Bs[64 * PB];   // 17KB
    int t = threadIdx.x;
    int lane = t & 31, warp = t >> 5;
    int wm = warp & 3, wn = warp >> 2;             // 4 (m) x 2 (n) warps
    int row0 = blockIdx.x * 128;

    float acc[2][8][4];
    #pragma unroll
    for (int mt = 0; mt < 2; mt++)
        #pragma unroll
        for (int nt = 0; nt < 8; nt++)
            #pragma unroll
            for (int d = 0; d < 4; d++) acc[mt][nt][d] = 0.f;

    int lm = lane >> 3, lr = lane & 7;

    for (int k0 = 0; k0 < 128; k0 += 64) {
        #pragma unroll
        for (int i = 0; i < 4; i++) {
            int lin = t + i * 256;                 // 0..1023
            int r = lin >> 3, c8 = (lin & 7) * 8;
            uint4 v = make_uint4(0u, 0u, 0u, 0u);
            if (row0 + r < NN)
                v = *(const uint4*)(g_ah + (size_t)(row0 + r) * 128 + k0 + c8);
            *(uint4*)(As + r * PA + c8) = v;
        }
        #pragma unroll
        for (int i = 0; i < 8; i++) {
            int lin = t + i * 256;                 // 0..2047
            int kk = lin >> 5, c4 = (lin & 31) * 4;
            float4 wv = *(const float4*)(W + (size_t)(k0 + kk) * 128 + c4);
            uint2 p;
            p.x = h2_as_u(__float22half2_rn(make_float2(wv.x, wv.y)));
            p.y = h2_as_u(__float22half2_rn(make_float2(wv.z, wv.w)));
            *(uint2*)(Bs + kk * PB + c4) = p;
        }
        __syncthreads();

        #pragma unroll
        for (int kk = 0; kk < 64; kk += 16) {
            unsigned a[2][4];
            #pragma unroll
            for (int mt = 0; mt < 2; mt++) {
                const __half* ap = As + (wm * 32 + mt * 16 + (lm & 1) * 8 + lr) * PA
                                      + kk + (lm >> 1) * 8;
                unsigned addr = (unsigned)__cvta_generic_to_shared(ap);
                asm volatile("ldmatrix.sync.aligned.m8n8.x4.shared.b16 {%0,%1,%2,%3}, [%4];"
                             : "=r"(a[mt][0]), "=r"(a[mt][1]), "=r"(a[mt][2]), "=r"(a[mt][3])
                             : "r"(addr));
            }
            unsigned b[8][2];
            #pragma unroll
            for (int nt16 = 0; nt16 < 4; nt16++) {
                const __half* bp = Bs + (kk + (lm & 1) * 8 + lr) * PB
                                      + wn * 64 + nt16 * 16 + (lm >> 1) * 8;
                unsigned addr = (unsigned)__cvta_generic_to_shared(bp);
                asm volatile("ldmatrix.sync.aligned.m8n8.x4.trans.shared.b16 {%0,%1,%2,%3}, [%4];"
                             : "=r"(b[2*nt16][0]), "=r"(b[2*nt16][1]),
                               "=r"(b[2*nt16+1][0]), "=r"(b[2*nt16+1][1])
                             : "r"(addr));
            }
            #pragma unroll
            for (int mt = 0; mt < 2; mt++)
                #pragma unroll
                for (int nt = 0; nt < 8; nt++) {
                    asm volatile(
                        "mma.sync.aligned.m16n8k16.row.col.f32.f16.f16.f32 "
                        "{%0,%1,%2,%3}, {%4,%5,%6,%7}, {%8,%9}, {%0,%1,%2,%3};"
                        : "+f"(acc[mt][nt][0]), "+f"(acc[mt][nt][1]),
                          "+f"(acc[mt][nt][2]), "+f"(acc[mt][nt][3])
                        : "r"(a[mt][0]), "r"(a[mt][1]), "r"(a[mt][2]), "r"(a[mt][3]),
                          "r"(b[nt][0]), "r"(b[nt][1]));
                }
        }
        __syncthreads();
    }

    // epilogue: bias + relu (+ optional dis row-scale) -> fp16 h
    #pragma unroll
    for (int nt = 0; nt < 8; nt++) {
        int col = wn * 64 + nt * 8 + (lane & 3) * 2;
        float2 bv = *(const float2*)(bias + col);
        #pragma unroll
        for (int mt = 0; mt < 2; mt++) {
            int rA = row0 + wm * 32 + mt * 16 + (lane >> 2);
            if (rA < NN) {
                float sc = scale_out ? g_dis[rA] : 1.f;
                float2 v = make_float2(sc * fmaxf(acc[mt][nt][0] + bv.x, 0.f),
                                       sc * fmaxf(acc[mt][nt][1] + bv.y, 0.f));
                *(__half2*)(g_hh + (size_t)rA * 128 + col) = __float22half2_rn(v);
            }
            int rB = rA + 8;
            if (rB < NN) {
                float sc = scale_out ? g_dis[rB] : 1.f;
                float2 v = make_float2(sc * fmaxf(acc[mt][nt][2] + bv.x, 0.f),
                                       sc * fmaxf(acc[mt][nt][3] + bv.y, 0.f));
                *(__half2*)(g_hh + (size_t)rB * 128 + col) = __float22half2_rn(v);
            }
        }
    }
}

// ---------------- fused mean-pool + classifier head ----------------
__global__ void k_poolfinal(const int* __restrict__ batch, const float* __restrict__ Wl,
                            const float* __restrict__ bl, float* __restrict__ out) {
    __shared__ float spool[128];
    int g = blockIdx.x;   // 0..127
    int c = threadIdx.x;  // 0..127
    int lo = 0, hi = NN;
    while (lo < hi) { int m = (lo + hi) >> 1; if (batch[m] < g) lo = m + 1; else hi = m; }
    int st = lo;
    lo = st; hi = NN;
    while (lo < hi) { int m = (lo + hi) >> 1; if (batch[m] < g + 1) lo = m + 1; else hi = m; }
    int en = lo;
    float s0 = 0.f, s1 = 0.f, s2 = 0.f, s3 = 0.f;
    int n = st;
    for (; n + 3 < en; n += 4) {
        s0 += __half2float(g_hh[(size_t)(n + 0) * 128 + c]);
        s1 += __half2float(g_hh[(size_t)(n + 1) * 128 + c]);
        s2 += __half2float(g_hh[(size_t)(n + 2) * 128 + c]);
        s3 += __half2float(g_hh[(size_t)(n + 3) * 128 + c]);
    }
    for (; n < en; n++) s0 += __half2float(g_hh[(size_t)n * 128 + c]);
    float s = (s0 + s1) + (s2 + s3);
    int cnt = en - st;
    spool[c] = s / (float)(cnt > 0 ? cnt : 1);
    __syncthreads();

    int lane = c & 31, warp = c >> 5;              // 4 warps
    for (int j = warp; j < NC; j += 4) {
        float p = 0.f;
        #pragma unroll
        for (int i = 0; i < 4; i++) {
            int k = lane + 32 * i;
            p += spool[k] * Wl[k * NC + j];
        }
        #pragma unroll
        for (int o = 16; o; o >>= 1) p += __shfl_down_sync(0xffffffffu, p, o);
        if (lane == 0) out[g * NC + j] = p + bl[j];
    }
}

extern "C" void kernel_launch(void* const* d_in, const int* in_sizes, int n_in,
                              void* d_out, int out_size) {
    const float* x     = (const float*)d_in[0];
    const int*   ei    = (const int*)d_in[1];
    const int*   batch = (const int*)d_in[2];
    const float* W1    = (const float*)d_in[3];
    const float* b1    = (const float*)d_in[4];
    const float* W2    = (const float*)d_in[5];
    const float* b2    = (const float*)d_in[6];
    const float* W3    = (const float*)d_in[7];
    const float* b3    = (const float*)d_in[8];
    const float* Wl    = (const float*)d_in[9];
    const float* bl    = (const float*)d_in[10];
    float* out = (float*)d_out;

    const int* src = ei;          // edge_index[0]
    const int* dst = ei + NE;     // edge_index[1]

    // CSR build: deg+slot assignment -> scan (lookback) -> atomic-free scatter
    k_deg  <<<(NE4 + 255) / 256, 256>>>(dst);
    k_scan1<<<NBLK, 256>>>(x);
    k_fill <<<(NE4 + 255) / 256, 256>>>(src, dst);

    // layer 1 -> g_hh (stores dis-scaled activations)
    k_layer1<<<(NN + 7) / 8, 256>>>(W1, b1);

    // layer 2 (epilogue stores dis-scaled)
    k_prop<<<(NN + 7) / 8, 256>>>();
    k_gemm<<<(NN + 127) / 128, 256>>>(W2, b2, 1);

    // layer 3 (plain activations for pooling)
    k_prop<<<(NN + 7) / 8, 256>>>();
    k_gemm<<<(NN + 127) / 128, 256>>>(W3, b3, 0);

    // pool + classifier head (fused)
    k_poolfinal<<<NG, HID>>>(batch, Wl, bl, out);
}

// round 16
// speedup vs baseline: 1.3566x; 1.3566x over previous
#include <cuda_runtime.h>
#include <cuda_fp16.h>

#define NN 50000
#define NE 600000
#define NT (NE + NN)
#define HID 128
#define NG 128
#define NC 5
#define NBLK ((NN + 255) / 256)   // 196

__device__ __forceinline__ unsigned h2_as_u(__half2 h) {
    return *reinterpret_cast<unsigned*>(&h);
}
__device__ __forceinline__ __half2 u_as_h2(unsigned u) {
    return *reinterpret_cast<__half2*>(&u);
}

// ---------------- device scratch (no allocs allowed) ----------------
__device__ int    g_cnt[NN];
__device__ float  g_dis[NN];
__device__ int    g_rowptr[NN + 1];
__device__ int    g_aggflag[NBLK];               // bit30 = ready, low bits = block agg
__device__ int    g_col[NT];                     // CSR columns (norm folded into nodes)
__device__ __align__(16) __half g_hh[NN * HID];  // buffer A
__device__ __align__(16) __half g_ah[NN * HID];  // buffer B

// ---------------- graph normalization ----------------
__global__ void k_init() {
    int i = blockIdx.x * blockDim.x + threadIdx.x;
    if (i < NN) g_cnt[i] = 1;  // self loop
    if (i < NBLK) g_aggflag[i] = 0;
}

__global__ void k_deg(const int* __restrict__ dst) {
    int e = blockIdx.x * blockDim.x + threadIdx.x;
    if (e < NE) atomicAdd(&g_cnt[dst[e]], 1);    // no return use -> RED
}

__device__ __forceinline__ int block_excl_scan_256(int v, int tid, int* wsum) {
    int lane = tid & 31, wid = tid >> 5;
    int x = v;
    #pragma unroll
    for (int o = 1; o < 32; o <<= 1) {
        int y = __shfl_up_sync(0xffffffffu, x, o);
        if (lane >= o) x += y;
    }
    if (lane == 31) wsum[wid] = x;
    __syncthreads();
    if (wid == 0) {
        int w = (lane < 8) ? wsum[lane] : 0;
        #pragma unroll
        for (int o = 1; o < 8; o <<= 1) {
            int y = __shfl_up_sync(0xffffffffu, w, o);
            if (lane >= o) w += y;
        }
        if (lane < 8) wsum[lane] = w;
    }
    __syncthreads();
    return x - v + (wid ? wsum[wid - 1] : 0);
}

// single-pass scan with lookback; computes dis, resets cnt (cursor for k_fill)
__global__ void k_scan1() {
    __shared__ int wsum[8];
    __shared__ int rsum[8];
    __shared__ int s_total;
    __shared__ int s_pre;
    int tid = threadIdx.x;
    int b = blockIdx.x;
    int i = b * 256 + tid;
    int v = 0;
    if (i < NN) {
        v = g_cnt[i];
        g_dis[i] = rsqrtf((float)v);
        g_cnt[i] = 0;                 // reused as cursor by k_fill
    }
    int excl = block_excl_scan_256(v, tid, wsum);
    if (tid == 255) s_total = excl + v;
    __syncthreads();
    if (tid == 0) atomicExch(&g_aggflag[b], 0x40000000 | s_total);
    int pre = 0;
    if (tid < b) {
        int f;
        do { f = atomicAdd(&g_aggflag[tid], 0); } while (!(f & 0x40000000));
        pre = f & 0x3fffffff;
    }
    int lane = tid & 31, wid = tid >> 5;
    #pragma unroll
    for (int o = 16; o; o >>= 1) pre += __shfl_down_sync(0xffffffffu, pre, o);
    if (lane == 0) rsum[wid] = pre;
    __syncthreads();
    if (wid == 0) {
        int w = (lane < 8) ? rsum[lane] : 0;
        #pragma unroll
        for (int o = 4; o; o >>= 1) w += __shfl_down_sync(0xffffffffu, w, o);
        if (lane == 0) s_pre = w;
    }
    __syncthreads();
    if (i < NN) g_rowptr[i] = excl + s_pre;
    if (b == 0 && tid == 0) g_rowptr[NN] = NT;
}

__global__ void k_fill(const int* __restrict__ src, const int* __restrict__ dst) {
    int t = blockIdx.x * blockDim.x + threadIdx.x;
    if (t >= NT) return;
    int s, d;
    if (t < NE) { s = src[t]; d = dst[t]; }
    else        { s = d = t - NE; }            // self loops
    int pos = atomicAdd(&g_cnt[d], 1);
    g_col[g_rowptr[d] + pos] = s;
}

// ---------------- y = (dis . x) @ W1  (dense, coalesced; no bias/relu yet) ----------------
__global__ void k_xw1(const float* __restrict__ x, const float* __restrict__ W1,
                      __half* __restrict__ yout) {
    int t = blockIdx.x * blockDim.x + threadIdx.x;
    if (t >= NN * 16) return;
    int node = t >> 4;
    int c8 = (t & 15) * 8;
    float dis = g_dis[node];
    float x0 = dis * x[node * 3 + 0];
    float x1 = dis * x[node * 3 + 1];
    float x2 = dis * x[node * 3 + 2];
    float4 wa0 = *(const float4*)(W1 + c8);         float4 wa1 = *(const float4*)(W1 + c8 + 4);
    float4 wb0 = *(const float4*)(W1 + 128 + c8);   float4 wb1 = *(const float4*)(W1 + 128 + c8 + 4);
    float4 wc0 = *(const float4*)(W1 + 256 + c8);   float4 wc1 = *(const float4*)(W1 + 256 + c8 + 4);
    float o[8];
    o[0] = x0 * wa0.x + x1 * wb0.x + x2 * wc0.x;
    o[1] = x0 * wa0.y + x1 * wb0.y + x2 * wc0.y;
    o[2] = x0 * wa0.z + x1 * wb0.z + x2 * wc0.z;
    o[3] = x0 * wa0.w + x1 * wb0.w + x2 * wc0.w;
    o[4] = x0 * wa1.x + x1 * wb1.x + x2 * wc1.x;
    o[5] = x0 * wa1.y + x1 * wb1.y + x2 * wc1.y;
    o[6] = x0 * wa1.z + x1 * wb1.z + x2 * wc1.z;
    o[7] = x0 * wa1.w + x1 * wb1.w + x2 * wc1.w;
    uint4 p;
    p.x = h2_as_u(__float22half2_rn(make_float2(o[0], o[1])));
    p.y = h2_as_u(__float22half2_rn(make_float2(o[2], o[3])));
    p.z = h2_as_u(__float22half2_rn(make_float2(o[4], o[5])));
    p.w = h2_as_u(__float22half2_rn(make_float2(o[6], o[7])));
    *(uint4*)(yout + (size_t)node * 128 + c8) = p;
}

// ---------------- propagate: hout[d] = f( dis[d] * sum_{s in N(d)} hin[s] ) ----------------
// mode 0: out = dis*sum          (pre-GEMM aggregate)
// mode 1: out = dis*relu(dis*sum + bias)   (layer-1 epilogue, stores dis-scaled h1)
__global__ void k_prop(const __half* __restrict__ hin, __half* __restrict__ hout,
                       const float* __restrict__ bias, int mode) {
    int node = blockIdx.x * 8 + (threadIdx.x >> 5);
    if (node >= NN) return;
    int lane = threadIdx.x & 31;
    int beg = g_rowptr[node], end = g_rowptr[node + 1];
    float4 acc  = make_float4(0.f, 0.f, 0.f, 0.f);
    float4 acc2 = make_float4(0.f, 0.f, 0.f, 0.f);
    int j = beg;
    for (; j + 3 < end; j += 4) {
        int s0c = g_col[j],     s1c = g_col[j + 1];
        int s2c = g_col[j + 2], s3c = g_col[j + 3];
        uint2 h0 = *(const uint2*)(hin + (size_t)s0c * 128 + lane * 4);
        uint2 h1 = *(const uint2*)(hin + (size_t)s1c * 128 + lane * 4);
        uint2 h2 = *(const uint2*)(hin + (size_t)s2c * 128 + lane * 4);
        uint2 h3 = *(const uint2*)(hin + (size_t)s3c * 128 + lane * 4);
        float2 p0 = __half22float2(u_as_h2(h0.x)), p1 = __half22float2(u_as_h2(h0.y));
        float2 q0 = __half22float2(u_as_h2(h1.x)), q1 = __half22float2(u_as_h2(h1.y));
        float2 r0 = __half22float2(u_as_h2(h2.x)), r1 = __half22float2(u_as_h2(h2.y));
        float2 t0 = __half22float2(u_as_h2(h3.x)), t1 = __half22float2(u_as_h2(h3.y));
        acc.x  += p0.x; acc.y  += p0.y; acc.z  += p1.x; acc.w  += p1.y;
        acc2.x += q0.x; acc2.y += q0.y; acc2.z += q1.x; acc2.w += q1.y;
        acc.x  += r0.x; acc.y  += r0.y; acc.z  += r1.x; acc.w  += r1.y;
        acc2.x += t0.x; acc2.y += t0.y; acc2.z += t1.x; acc2.w += t1.y;
    }
    for (; j < end; j++) {
        uint2 h = *(const uint2*)(hin + (size_t)g_col[j] * 128 + lane * 4);
        float2 p0 = __half22float2(u_as_h2(h.x));
        float2 p1 = __half22float2(u_as_h2(h.y));
        acc.x += p0.x; acc.y += p0.y; acc.z += p1.x; acc.w += p1.y;
    }
    float dis = g_dis[node];
    acc.x = (acc.x + acc2.x) * dis; acc.y = (acc.y + acc2.y) * dis;
    acc.z = (acc.z + acc2.z) * dis; acc.w = (acc.w + acc2.w) * dis;
    if (mode == 1) {
        float4 bv = *(const float4*)(bias + lane * 4);
        acc.x = dis * fmaxf(acc.x + bv.x, 0.f);
        acc.y = dis * fmaxf(acc.y + bv.y, 0.f);
        acc.z = dis * fmaxf(acc.z + bv.z, 0.f);
        acc.w = dis * fmaxf(acc.w + bv.w, 0.f);
    }
    uint2 o;
    o.x = h2_as_u(__float22half2_rn(make_float2(acc.x, acc.y)));
    o.y = h2_as_u(__float22half2_rn(make_float2(acc.z, acc.w)));
    *(uint2*)(hout + (size_t)node * 128 + lane * 4) = o;
}

// ---------------- GEMM (HMMA): g_hh = [dis*] relu(g_ah @ W + b) ----------------
#define PA 72    // A smem pitch (halfs)
#define PB 136   // B smem pitch (halfs)

__global__ __launch_bounds__(256, 2) void k_gemm(const float* __restrict__ W,
                                                 const float* __restrict__ bias,
                                                 int scale_out) {
    __shared__ __align__(16) __half As[128 * PA];  // 18KB
    __shared__ __align__(16) __half Bs[64 * PB];   // 17KB
    int t = threadIdx.x;
    int lane = t & 31, warp = t >> 5;
    int wm = warp & 3, wn = warp >> 2;             // 4 (m) x 2 (n) warps
    int row0 = blockIdx.x * 128;

    float acc[2][8][4];
    #pragma unroll
    for (int mt = 0; mt < 2; mt++)
        #pragma unroll
        for (int nt = 0; nt < 8; nt++)
            #pragma unroll
            for (int d = 0; d < 4; d++) acc[mt][nt][d] = 0.f;

    int lm = lane >> 3, lr = lane & 7;

    for (int k0 = 0; k0 < 128; k0 += 64) {
        #pragma unroll
        for (int i = 0; i < 4; i++) {
            int lin = t + i * 256;                 // 0..1023
            int r = lin >> 3, c8 = (lin & 7) * 8;
            uint4 v = make_uint4(0u, 0u, 0u, 0u);
            if (row0 + r < NN)
                v = *(const uint4*)(g_ah + (size_t)(row0 + r) * 128 + k0 + c8);
            *(uint4*)(As + r * PA + c8) = v;
        }
        #pragma unroll
        for (int i = 0; i < 8; i++) {
            int lin = t + i * 256;                 // 0..2047
            int kk = lin >> 5, c4 = (lin & 31) * 4;
            float4 wv = *(const float4*)(W + (size_t)(k0 + kk) * 128 + c4);
            uint2 p;
            p.x = h2_as_u(__float22half2_rn(make_float2(wv.x, wv.y)));
            p.y = h2_as_u(__float22half2_rn(make_float2(wv.z, wv.w)));
            *(uint2*)(Bs + kk * PB + c4) = p;
        }
        __syncthreads();

        #pragma unroll
        for (int kk = 0; kk < 64; kk += 16) {
            unsigned a[2][4];
            #pragma unroll
            for (int mt = 0; mt < 2; mt++) {
                const __half* ap = As + (wm * 32 + mt * 16 + (lm & 1) * 8 + lr) * PA
                                      + kk + (lm >> 1) * 8;
                unsigned addr = (unsigned)__cvta_generic_to_shared(ap);
                asm volatile("ldmatrix.sync.aligned.m8n8.x4.shared.b16 {%0,%1,%2,%3}, [%4];"
                             : "=r"(a[mt][0]), "=r"(a[mt][1]), "=r"(a[mt][2]), "=r"(a[mt][3])
                             : "r"(addr));
            }
            unsigned b[8][2];
            #pragma unroll
            for (int nt16 = 0; nt16 < 4; nt16++) {
                const __half* bp = Bs + (kk + (lm & 1) * 8 + lr) * PB
                                      + wn * 64 + nt16 * 16 + (lm >> 1) * 8;
                unsigned addr = (unsigned)__cvta_generic_to_shared(bp);
                asm volatile("ldmatrix.sync.aligned.m8n8.x4.trans.shared.b16 {%0,%1,%2,%3}, [%4];"
                             : "=r"(b[2*nt16][0]), "=r"(b[2*nt16][1]),
                               "=r"(b[2*nt16+1][0]), "=r"(b[2*nt16+1][1])
                             : "r"(addr));
            }
            #pragma unroll
            for (int mt = 0; mt < 2; mt++)
                #pragma unroll
                for (int nt = 0; nt < 8; nt++) {
                    asm volatile(
                        "mma.sync.aligned.m16n8k16.row.col.f32.f16.f16.f32 "
                        "{%0,%1,%2,%3}, {%4,%5,%6,%7}, {%8,%9}, {%0,%1,%2,%3};"
                        : "+f"(acc[mt][nt][0]), "+f"(acc[mt][nt][1]),
                          "+f"(acc[mt][nt][2]), "+f"(acc[mt][nt][3])
                        : "r"(a[mt][0]), "r"(a[mt][1]), "r"(a[mt][2]), "r"(a[mt][3]),
                          "r"(b[nt][0]), "r"(b[nt][1]));
                }
        }
        __syncthreads();
    }

    // epilogue: bias + relu (+ optional dis row-scale) -> fp16 h
    #pragma unroll
    for (int nt = 0; nt < 8; nt++) {
        int col = wn * 64 + nt * 8 + (lane & 3) * 2;
        float2 bv = *(const float2*)(bias + col);
        #pragma unroll
        for (int mt = 0; mt < 2; mt++) {
            int rA = row0 + wm * 32 + mt * 16 + (lane >> 2);
            if (rA < NN) {
                float sc = scale_out ? g_dis[rA] : 1.f;
                float2 v = make_float2(sc * fmaxf(acc[mt][nt][0] + bv.x, 0.f),
                                       sc * fmaxf(acc[mt][nt][1] + bv.y, 0.f));
                *(__half2*)(g_hh + (size_t)rA * 128 + col) = __float22half2_rn(v);
            }
            int rB = rA + 8;
            if (rB < NN) {
                float sc = scale_out ? g_dis[rB] : 1.f;
                float2 v = make_float2(sc * fmaxf(acc[mt][nt][2] + bv.x, 0.f),
                                       sc * fmaxf(acc[mt][nt][3] + bv.y, 0.f));
                *(__half2*)(g_hh + (size_t)rB * 128 + col) = __float22half2_rn(v);
            }
        }
    }
}

// ---------------- fused mean-pool + classifier head ----------------
__global__ void k_poolfinal(const int* __restrict__ batch, const float* __restrict__ Wl,
                            const float* __restrict__ bl, float* __restrict__ out) {
    __shared__ float spool[128];
    int g = blockIdx.x;   // 0..127
    int c = threadIdx.x;  // 0..127
    int lo = 0, hi = NN;
    while (lo < hi) { int m = (lo + hi) >> 1; if (batch[m] < g) lo = m + 1; else hi = m; }
    int st = lo;
    lo = st; hi = NN;
    while (lo < hi) { int m = (lo + hi) >> 1; if (batch[m] < g + 1) lo = m + 1; else hi = m; }
    int en = lo;
    float s0 = 0.f, s1 = 0.f, s2 = 0.f, s3 = 0.f;
    int n = st;
    for (; n + 3 < en; n += 4) {
        s0 += __half2float(g_hh[(size_t)(n + 0) * 128 + c]);
        s1 += __half2float(g_hh[(size_t)(n + 1) * 128 + c]);
        s2 += __half2float(g_hh[(size_t)(n + 2) * 128 + c]);
        s3 += __half2float(g_hh[(size_t)(n + 3) * 128 + c]);
    }
    for (; n < en; n++) s0 += __half2float(g_hh[(size_t)n * 128 + c]);
    float s = (s0 + s1) + (s2 + s3);
    int cnt = en - st;
    spool[c] = s / (float)(cnt > 0 ? cnt : 1);
    __syncthreads();

    int lane = c & 31, warp = c >> 5;              // 4 warps
    for (int j = warp; j < NC; j += 4) {
        float p = 0.f;
        #pragma unroll
        for (int i = 0; i < 4; i++) {
            int k = lane + 32 * i;
            p += spool[k] * Wl[k * NC + j];
        }
        #pragma unroll
        for (int o = 16; o; o >>= 1) p += __shfl_down_sync(0xffffffffu, p, o);
        if (lane == 0) out[g * NC + j] = p + bl[j];
    }
}

extern "C" void kernel_launch(void* const* d_in, const int* in_sizes, int n_in,
                              void* d_out, int out_size) {
    const float* x     = (const float*)d_in[0];
    const int*   ei    = (const int*)d_in[1];
    const int*   batch = (const int*)d_in[2];
    const float* W1    = (const float*)d_in[3];
    const float* b1    = (const float*)d_in[4];
    const float* W2    = (const float*)d_in[5];
    const float* b2    = (const float*)d_in[6];
    const float* W3    = (const float*)d_in[7];
    const float* b3    = (const float*)d_in[8];
    const float* Wl    = (const float*)d_in[9];
    const float* bl    = (const float*)d_in[10];
    float* out = (float*)d_out;

    const int* src = ei;          // edge_index[0]
    const int* dst = ei + NE;     // edge_index[1]

    __half *hh_p = nullptr, *ah_p = nullptr;
    cudaGetSymbolAddress((void**)&hh_p, g_hh);
    cudaGetSymbolAddress((void**)&ah_p, g_ah);

    // graph norm + CSR build (R14-proven path)
    k_init <<<(NN + 255) / 256, 256>>>();
    k_deg  <<<(NE + 255) / 256, 256>>>(dst);
    k_scan1<<<NBLK, 256>>>();
    k_fill <<<(NT + 255) / 256, 256>>>(src, dst);

    // layer 1: y = (dis.x)@W1 (dense), then 128-wide prop with fused bias/relu/scale
    k_xw1 <<<(NN * 16 + 255) / 256, 256>>>(x, W1, ah_p);          // y -> g_ah
    k_prop<<<(NN + 7) / 8, 256>>>(ah_p, hh_p, b1, 1);             // h1' -> g_hh

    // layer 2 (epilogue stores dis-scaled)
    k_prop<<<(NN + 7) / 8, 256>>>(hh_p, ah_p, nullptr, 0);
    k_gemm<<<(NN + 127) / 128, 256>>>(W2, b2, 1);

    // layer 3 (plain activations for pooling)
    k_prop<<<(NN + 7) / 8, 256>>>(hh_p, ah_p, nullptr, 0);
    k_gemm<<<(NN + 127) / 128, 256>>>(W3, b3, 0);

    // pool + classifier head (fused)
    k_poolfinal<<<NG, HID>>>(batch, Wl, bl, out);
}

// round 17
// speedup vs baseline: 1.3660x; 1.0069x over previous
#include <cuda_runtime.h>
#include <cuda_fp16.h>

#define NN 50000
#define NE 600000
#define NT (NE + NN)
#define HID 128
#define NG 128
#define NC 5
#define NBLK ((NN + 255) / 256)   // 196 scan blocks
#define NBB 640                   // build grid (co-resident: <= 148*5)
#define NGRP (NBB / 32)           // 20 barrier groups

__device__ __forceinline__ unsigned h2_as_u(__half2 h) {
    return *reinterpret_cast<unsigned*>(&h);
}
__device__ __forceinline__ __half2 u_as_h2(unsigned u) {
    return *reinterpret_cast<__half2*>(&u);
}

// ---------------- device scratch (no allocs allowed) ----------------
// invariant: g_cnt all-zero on entry (zero-init at load; k_poolfinal restores)
__device__ int      g_cnt[NN];
__device__ float    g_dis[NN];
__device__ int      g_rowptr[NN + 1];
__device__ int      g_aggflag[NBLK];
__device__ int      g_col[NT];
__device__ __align__(16) float4 g_xs4[NN];       // dis[n]*x[n] padded
__device__ __align__(16) __half g_hh[NN * HID];
__device__ __align__(16) __half g_ah[NN * HID];
// grid-barrier state (self-restoring: counters return to 0, gen monotone)
__device__ unsigned g_bargen = 0;
__device__ unsigned g_barc1[NGRP];
__device__ unsigned g_barc0 = 0;

__device__ __forceinline__ void gridbar() {
    __syncthreads();
    if (threadIdx.x == 0) {
        unsigned gen = *((volatile unsigned*)&g_bargen);
        __threadfence();
        int grp = blockIdx.x >> 5;
        if (atomicAdd(&g_barc1[grp], 1) == 31) {
            if (atomicAdd(&g_barc0, 1) == NGRP - 1) {
                g_barc0 = 0;
                #pragma unroll
                for (int i = 0; i < NGRP; i++) g_barc1[i] = 0;
                __threadfence();
                atomicAdd(&g_bargen, 1);
            }
        }
        while (*((volatile unsigned*)&g_bargen) == gen) { __nanosleep(64); }
    }
    __syncthreads();
    __threadfence();
}

__device__ __forceinline__ int block_excl_scan_256(int v, int tid, int* wsum) {
    int lane = tid & 31, wid = tid >> 5;
    int x = v;
    #pragma unroll
    for (int o = 1; o < 32; o <<= 1) {
        int y = __shfl_up_sync(0xffffffffu, x, o);
        if (lane >= o) x += y;
    }
    if (lane == 31) wsum[wid] = x;
    __syncthreads();
    if (wid == 0) {
        int w = (lane < 8) ? wsum[lane] : 0;
        #pragma unroll
        for (int o = 1; o < 8; o <<= 1) {
            int y = __shfl_up_sync(0xffffffffu, w, o);
            if (lane >= o) w += y;
        }
        if (lane < 8) wsum[lane] = w;
    }
    __syncthreads();
    return x - v + (wid ? wsum[wid - 1] : 0);
}

// ---------------- fused CSR build: deg -> scan(lookback) -> fill ----------------
__global__ __launch_bounds__(256, 5) void k_build(const float* __restrict__ x,
                                                  const int* __restrict__ src,
                                                  const int* __restrict__ dst) {
    __shared__ int wsum[8];
    __shared__ int rsum[8];
    __shared__ int s_total;
    __shared__ int s_pre;
    int tid = threadIdx.x;
    int b = blockIdx.x;
    int gt = b * 256 + tid;

    // phase A: degree count (RED, no return) + aggflag reset
    if (gt < NBLK) g_aggflag[gt] = 0;
    for (int e = gt; e < NE; e += NBB * 256)
        atomicAdd(&g_cnt[dst[e]], 1);

    gridbar();

    // phase B: lookback scan over first NBLK blocks; dis, xs4, self-loop slot 0
    if (b < NBLK) {
        int i = gt;
        int v = 0;
        if (i < NN) {
            v = g_cnt[i] + 1;         // +1 self loop
            float dis = rsqrtf((float)v);
            g_dis[i] = dis;
            g_xs4[i] = make_float4(dis * x[i * 3 + 0], dis * x[i * 3 + 1],
                                   dis * x[i * 3 + 2], 0.f);
            g_cnt[i] = 0;             // cursor for phase C
        }
        int excl = block_excl_scan_256(v, tid, wsum);
        if (tid == 255) s_total = excl + v;
        __syncthreads();
        if (tid == 0) atomicExch(&g_aggflag[b], 0x40000000 | s_total);
        int pre = 0;
        if (tid < b) {
            int f;
            do { f = atomicAdd(&g_aggflag[tid], 0); } while (!(f & 0x40000000));
            pre = f & 0x3fffffff;
        }
        int lane = tid & 31, wid = tid >> 5;
        #pragma unroll
        for (int o = 16; o; o >>= 1) pre += __shfl_down_sync(0xffffffffu, pre, o);
        if (lane == 0) rsum[wid] = pre;
        __syncthreads();
        if (wid == 0) {
            int w = (lane < 8) ? rsum[lane] : 0;
            #pragma unroll
            for (int o = 4; o; o >>= 1) w += __shfl_down_sync(0xffffffffu, w, o);
            if (lane == 0) s_pre = w;
        }
        __syncthreads();
        if (i < NN) {
            int rp = excl + s_pre;
            g_rowptr[i] = rp;
            g_col[rp] = i;            // self loop at slot 0
        }
        if (b == 0 && tid == 0) g_rowptr[NN] = NT;
    }

    gridbar();

    // phase C: scatter edges (cursor atomics; leaves g_cnt = deg, reset by poolfinal)
    for (int e = gt; e < NE; e += NBB * 256) {
        int s = src[e];
        int d = dst[e];
        int p = atomicAdd(&g_cnt[d], 1);
        g_col[g_rowptr[d] + 1 + p] = s;
    }
}

// ---------------- layer 1: h1' = dis * relu( dis*(sum xs4) @ W1 + b1 ) ----------------
__global__ void k_layer1(const float* __restrict__ W1, const float* __restrict__ b1) {
    int node = blockIdx.x * 8 + (threadIdx.x >> 5);
    if (node >= NN) return;
    int lane = threadIdx.x & 31;
    int beg = g_rowptr[node], end = g_rowptr[node + 1];
    float a0 = 0.f, a1 = 0.f, a2 = 0.f;
    for (int j = beg + lane; j < end; j += 32) {
        float4 v = g_xs4[g_col[j]];
        a0 += v.x; a1 += v.y; a2 += v.z;
    }
    #pragma unroll
    for (int o = 16; o; o >>= 1) {
        a0 += __shfl_down_sync(0xffffffffu, a0, o);
        a1 += __shfl_down_sync(0xffffffffu, a1, o);
        a2 += __shfl_down_sync(0xffffffffu, a2, o);
    }
    float dis = g_dis[node];
    a0 = __shfl_sync(0xffffffffu, a0, 0) * dis;
    a1 = __shfl_sync(0xffffffffu, a1, 0) * dis;
    a2 = __shfl_sync(0xffffffffu, a2, 0) * dis;
    int c = lane * 4;
    float v0 = dis * fmaxf(a0 * W1[c+0] + a1 * W1[128+c+0] + a2 * W1[256+c+0] + b1[c+0], 0.f);
    float v1 = dis * fmaxf(a0 * W1[c+1] + a1 * W1[128+c+1] + a2 * W1[256+c+1] + b1[c+1], 0.f);
    float v2 = dis * fmaxf(a0 * W1[c+2] + a1 * W1[128+c+2] + a2 * W1[256+c+2] + b1[c+2], 0.f);
    float v3 = dis * fmaxf(a0 * W1[c+3] + a1 * W1[128+c+3] + a2 * W1[256+c+3] + b1[c+3], 0.f);
    uint2 p;
    p.x = h2_as_u(__float22half2_rn(make_float2(v0, v1)));
    p.y = h2_as_u(__float22half2_rn(make_float2(v2, v3)));
    *(uint2*)(g_hh + (size_t)node * 128 + c) = p;
}

// ---------------- propagate: g_ah[d] = dis[d] * sum_{s in N(d)} g_hh[s] ----------------
__global__ void k_prop() {
    int node = blockIdx.x * 8 + (threadIdx.x >> 5);
    if (node >= NN) return;
    int lane = threadIdx.x & 31;
    int beg = g_rowptr[node], end = g_rowptr[node + 1];
    float4 acc  = make_float4(0.f, 0.f, 0.f, 0.f);
    float4 acc2 = make_float4(0.f, 0.f, 0.f, 0.f);
    int j = beg;
    for (; j + 3 < end; j += 4) {
        int s0c = g_col[j],     s1c = g_col[j + 1];
        int s2c = g_col[j + 2], s3c = g_col[j + 3];
        uint2 h0 = *(const uint2*)(g_hh + (size_t)s0c * 128 + lane * 4);
        uint2 h1 = *(const uint2*)(g_hh + (size_t)s1c * 128 + lane * 4);
        uint2 h2 = *(const uint2*)(g_hh + (size_t)s2c * 128 + lane * 4);
        uint2 h3 = *(const uint2*)(g_hh + (size_t)s3c * 128 + lane * 4);
        float2 p0 = __half22float2(u_as_h2(h0.x)), p1 = __half22float2(u_as_h2(h0.y));
        float2 q0 = __half22float2(u_as_h2(h1.x)), q1 = __half22float2(u_as_h2(h1.y));
        float2 r0 = __half22float2(u_as_h2(h2.x)), r1 = __half22float2(u_as_h2(h2.y));
        float2 t0 = __half22float2(u_as_h2(h3.x)), t1 = __half22float2(u_as_h2(h3.y));
        acc.x  += p0.x; acc.y  += p0.y; acc.z  += p1.x; acc.w  += p1.y;
        acc2.x += q0.x; acc2.y += q0.y; acc2.z += q1.x; acc2.w += q1.y;
        acc.x  += r0.x; acc.y  += r0.y; acc.z  += r1.x; acc.w  += r1.y;
        acc2.x += t0.x; acc2.y += t0.y; acc2.z += t1.x; acc2.w += t1.y;
    }
    for (; j < end; j++) {
        uint2 h = *(const uint2*)(g_hh + (size_t)g_col[j] * 128 + lane * 4);
        float2 p0 = __half22float2(u_as_h2(h.x));
        float2 p1 = __half22float2(u_as_h2(h.y));
        acc.x += p0.x; acc.y += p0.y; acc.z += p1.x; acc.w += p1.y;
    }
    float dis = g_dis[node];
    acc.x = (acc.x + acc2.x) * dis; acc.y = (acc.y + acc2.y) * dis;
    acc.z = (acc.z + acc2.z) * dis; acc.w = (acc.w + acc2.w) * dis;
    uint2 o;
    o.x = h2_as_u(__float22half2_rn(make_float2(acc.x, acc.y)));
    o.y = h2_as_u(__float22half2_rn(make_float2(acc.z, acc.w)));
    *(uint2*)(g_ah + (size_t)node * 128 + lane * 4) = o;
}

// ---------------- GEMM (HMMA): g_hh = [dis*] relu(g_ah @ W + b) ----------------
#define PA 72
#define PB 136

__global__ __launch_bounds__(256, 2) void k_gemm(const float* __restrict__ W,
                                                 const float* __restrict__ bias,
                                                 int scale_out) {
    __shared__ __align__(16) __half As[128 * PA];
    __shared__ __align__(16) __half Bs[64 * PB];
    int t = threadIdx.x;
    int lane = t & 31, warp = t >> 5;
    int wm = warp & 3, wn = warp >> 2;
    int row0 = blockIdx.x * 128;

    float acc[2][8][4];
    #pragma unroll
    for (int mt = 0; mt < 2; mt++)
        #pragma unroll
        for (int nt = 0; nt < 8; nt++)
            #pragma unroll
            for (int d = 0; d < 4; d++) acc[mt][nt][d] = 0.f;

    int lm = lane >> 3, lr = lane & 7;

    for (int k0 = 0; k0 < 128; k0 += 64) {
        #pragma unroll
        for (int i = 0; i < 4; i++) {
            int lin = t + i * 256;
            int r = lin >> 3, c8 = (lin & 7) * 8;
            uint4 v = make_uint4(0u, 0u, 0u, 0u);
            if (row0 + r < NN)
                v = *(const uint4*)(g_ah + (size_t)(row0 + r) * 128 + k0 + c8);
            *(uint4*)(As + r * PA + c8) = v;
        }
        #pragma unroll
        for (int i = 0; i < 8; i++) {
            int lin = t + i * 256;
            int kk = lin >> 5, c4 = (lin & 31) * 4;
            float4 wv = *(const float4*)(W + (size_t)(k0 + kk) * 128 + c4);
            uint2 p;
            p.x = h2_as_u(__float22half2_rn(make_float2(wv.x, wv.y)));
            p.y = h2_as_u(__float22half2_rn(make_float2(wv.z, wv.w)));
            *(uint2*)(Bs + kk * PB + c4) = p;
        }
        __syncthreads();

        #pragma unroll
        for (int kk = 0; kk < 64; kk += 16) {
            unsigned a[2][4];
            #pragma unroll
            for (int mt = 0; mt < 2; mt++) {
                const __half* ap = As + (wm * 32 + mt * 16 + (lm & 1) * 8 + lr) * PA
                                      + kk + (lm >> 1) * 8;
                unsigned addr = (unsigned)__cvta_generic_to_shared(ap);
                asm volatile("ldmatrix.sync.aligned.m8n8.x4.shared.b16 {%0,%1,%2,%3}, [%4];"
                             : "=r"(a[mt][0]), "=r"(a[mt][1]), "=r"(a[mt][2]), "=r"(a[mt][3])
                             : "r"(addr));
            }
            unsigned b[8][2];
            #pragma unroll
            for (int nt16 = 0; nt16 < 4; nt16++) {
                const __half* bp = Bs + (kk + (lm & 1) * 8 + lr) * PB
                                      + wn * 64 + nt16 * 16 + (lm >> 1) * 8;
                unsigned addr = (unsigned)__cvta_generic_to_shared(bp);
                asm volatile("ldmatrix.sync.aligned.m8n8.x4.trans.shared.b16 {%0,%1,%2,%3}, [%4];"
                             : "=r"(b[2*nt16][0]), "=r"(b[2*nt16][1]),
                               "=r"(b[2*nt16+1][0]), "=r"(b[2*nt16+1][1])
                             : "r"(addr));
            }
            #pragma unroll
            for (int mt = 0; mt < 2; mt++)
                #pragma unroll
                for (int nt = 0; nt < 8; nt++) {
                    asm volatile(
                        "mma.sync.aligned.m16n8k16.row.col.f32.f16.f16.f32 "
                        "{%0,%1,%2,%3}, {%4,%5,%6,%7}, {%8,%9}, {%0,%1,%2,%3};"
                        : "+f"(acc[mt][nt][0]), "+f"(acc[mt][nt][1]),
                          "+f"(acc[mt][nt][2]), "+f"(acc[mt][nt][3])
                        : "r"(a[mt][0]), "r"(a[mt][1]), "r"(a[mt][2]), "r"(a[mt][3]),
                          "r"(b[nt][0]), "r"(b[nt][1]));
                }
        }
        __syncthreads();
    }

    #pragma unroll
    for (int nt = 0; nt < 8; nt++) {
        int col = wn * 64 + nt * 8 + (lane & 3) * 2;
        float2 bv = *(const float2*)(bias + col);
        #pragma unroll
        for (int mt = 0; mt < 2; mt++) {
            int rA = row0 + wm * 32 + mt * 16 + (lane >> 2);
            if (rA < NN) {
                float sc = scale_out ? g_dis[rA] : 1.f;
                float2 v = make_float2(sc * fmaxf(acc[mt][nt][0] + bv.x, 0.f),
                                       sc * fmaxf(acc[mt][nt][1] + bv.y, 0.f));
                *(__half2*)(g_hh + (size_t)rA * 128 + col) = __float22half2_rn(v);
            }
            int rB = rA + 8;
            if (rB < NN) {
                float sc = scale_out ? g_dis[rB] : 1.f;
                float2 v = make_float2(sc * fmaxf(acc[mt][nt][2] + bv.x, 0.f),
                                       sc * fmaxf(acc[mt][nt][3] + bv.y, 0.f));
                *(__half2*)(g_hh + (size_t)rB * 128 + col) = __float22half2_rn(v);
            }
        }
    }
}

// ---------------- fused mean-pool + classifier head (+ g_cnt invariant restore) ----------------
__global__ void k_poolfinal(const int* __restrict__ batch, const float* __restrict__ Wl,
                            const float* __restrict__ bl, float* __restrict__ out) {
    __shared__ float spool[128];
    // restore g_cnt == 0 invariant for the next call (phase C left it = deg)
    for (int i = blockIdx.x * 128 + threadIdx.x; i < NN; i += NG * 128)
        g_cnt[i] = 0;
    int g = blockIdx.x;
    int c = threadIdx.x;
    int lo = 0, hi = NN;
    while (lo < hi) { int m = (lo + hi) >> 1; if (batch[m] < g) lo = m + 1; else hi = m; }
    int st = lo;
    lo = st; hi = NN;
    while (lo < hi) { int m = (lo + hi) >> 1; if (batch[m] < g + 1) lo = m + 1; else hi = m; }
    int en = lo;
    float s0 = 0.f, s1 = 0.f, s2 = 0.f, s3 = 0.f;
    int n = st;
    for (; n + 3 < en; n += 4) {
        s0 += __half2float(g_hh[(size_t)(n + 0) * 128 + c]);
        s1 += __half2float(g_hh[(size_t)(n + 1) * 128 + c]);
        s2 += __half2float(g_hh[(size_t)(n + 2) * 128 + c]);
        s3 += __half2float(g_hh[(size_t)(n + 3) * 128 + c]);
    }
    for (; n < en; n++) s0 += __half2float(g_hh[(size_t)n * 128 + c]);
    float s = (s0 + s1) + (s2 + s3);
    int cnt = en - st;
    spool[c] = s / (float)(cnt > 0 ? cnt : 1);
    __syncthreads();

    int lane = c & 31, warp = c >> 5;
    for (int j = warp; j < NC; j += 4) {
        float p = 0.f;
        #pragma unroll
        for (int i = 0; i < 4; i++) {
            int k = lane + 32 * i;
            p += spool[k] * Wl[k * NC + j];
        }
        #pragma unroll
        for (int o = 16; o; o >>= 1) p += __shfl_down_sync(0xffffffffu, p, o);
        if (lane == 0) out[g * NC + j] = p + bl[j];
    }
}

extern "C" void kernel_launch(void* const* d_in, const int* in_sizes, int n_in,
                              void* d_out, int out_size) {
    const float* x     = (const float*)d_in[0];
    const int*   ei    = (const int*)d_in[1];
    const int*   batch = (const int*)d_in[2];
    const float* W1    = (const float*)d_in[3];
    const float* b1    = (const float*)d_in[4];
    const float* W2    = (const float*)d_in[5];
    const float* b2    = (const float*)d_in[6];
    const float* W3    = (const float*)d_in[7];
    const float* b3    = (const float*)d_in[8];
    const float* Wl    = (const float*)d_in[9];
    const float* bl    = (const float*)d_in[10];
    float* out = (float*)d_out;

    const int* src = ei;          // edge_index[0]
    const int* dst = ei + NE;     // edge_index[1]

    // fused CSR build (deg + lookback scan + fill, 2 internal grid barriers)
    k_build<<<NBB, 256>>>(x, src, dst);

    // layer 1 -> g_hh (dis-scaled activations)
    k_layer1<<<(NN + 7) / 8, 256>>>(W1, b1);

    // layer 2
    k_prop<<<(NN + 7) / 8, 256>>>();
    k_gemm<<<(NN + 127) / 128, 256>>>(W2, b2, 1);

    // layer 3
    k_prop<<<(NN + 7) / 8, 256>>>();
    k_gemm<<<(NN + 127) / 128, 256>>>(W3, b3, 0);

    // pool + classifier head (+ cnt reset)
    k_poolfinal<<<NG, HID>>>(batch, Wl, bl, out);
}